// round 8
// baseline (speedup 1.0000x reference)
#include <cuda_runtime.h>
#include <math.h>
#include <cstdint>

#define ADAPTERS 40
#define CAPS 3
#define CLASS_DIM 200
#define IN_CH 600
#define BATCH 256
#define DHID 768
#define NFUSED (CAPS * CLASS_DIM)  // 600

// Scratch (static device arrays -- no allocation at runtime)
__device__ float g_BT[ADAPTERS * CAPS * CLASS_DIM * IN_CH];  // [k*3+n][d][c]
__device__ float g_P[CAPS * ADAPTERS * BATCH * CLASS_DIM];   // [n][k][b][d], zero for k>t
__device__ float g_V[CAPS * BATCH * CLASS_DIM];              // [n][b][d] flat

// ---------------------------------------------------------------------------
// tf32 helpers (legacy mma.sync path -- compiles for plain sm_103, no 'a' feat)
// ---------------------------------------------------------------------------
__device__ __forceinline__ uint32_t tf32_rna(float x) {
    uint32_t r;
    asm("cvt.rna.tf32.f32 %0, %1;" : "=r"(r) : "f"(x));
    return r;
}
__device__ __forceinline__ void mma_tf32(float* c, const uint32_t a0, const uint32_t a1,
                                         const uint32_t a2, const uint32_t a3,
                                         const uint32_t b0, const uint32_t b1) {
    asm volatile(
        "mma.sync.aligned.m16n8k8.row.col.f32.tf32.tf32.f32 "
        "{%0,%1,%2,%3}, {%4,%5,%6,%7}, {%8,%9}, {%0,%1,%2,%3};"
        : "+f"(c[0]), "+f"(c[1]), "+f"(c[2]), "+f"(c[3])
        : "r"(a0), "r"(a1), "r"(a2), "r"(a3), "r"(b0), "r"(b1));
}

// ---------------------------------------------------------------------------
// Kernel 0: B transpose: rw[kn] (600c x 200d, d contiguous) -> g_BT[kn] (200d x 600c)
// ---------------------------------------------------------------------------
__global__ void k_btrans(const float* __restrict__ rw, const int* __restrict__ tptr) {
    int kn = blockIdx.x;
    if (kn / 3 > *tptr) return;
    __shared__ float tile[32][33];
    int c0 = blockIdx.y * 32, d0 = blockIdx.z * 32;
    int tx = threadIdx.x, ty = threadIdx.y;  // (32,8)
#pragma unroll
    for (int i = 0; i < 4; i++) {
        int c = c0 + ty + i * 8, d = d0 + tx;
        float v = 0.f;
        if (c < IN_CH && d < CLASS_DIM) v = rw[((size_t)kn * IN_CH + c) * CLASS_DIM + d];
        tile[ty + i * 8][tx] = v;
    }
    __syncthreads();
#pragma unroll
    for (int i = 0; i < 4; i++) {
        int d = d0 + ty + i * 8, c = c0 + tx;
        if (d < CLASS_DIM && c < IN_CH)
            g_BT[((size_t)kn * CLASS_DIM + d) * IN_CH + c] = tile[tx][ty + i * 8];
    }
}

// ---------------------------------------------------------------------------
// Kernel 1: priors GEMM via legacy tensor path: mma.sync m16n8k8 tf32 with
// 3-term split (hihi + lohi + hilo), fp32 accumulate. Per CTA (k<=t, mhalf,
// fused-n block): C[128x64] = A[128x600] @ B[600x64]. 75 K-steps of 8.
// 128 threads = 4 warps (2m x 2n), warp tile 64x32 (4x4 micro-tiles).
// Smem row pitch 12 words (48B) -> all LDS/STS phases bank-conflict-free.
// ---------------------------------------------------------------------------
#define PITCH 12
#define AHI 0
#define ALO (128 * PITCH)            // 1536
#define BHI (2 * 128 * PITCH)        // 3072
#define BLO (2 * 128 * PITCH + 64 * PITCH)  // 3840
#define BUFW (2 * 128 * PITCH + 2 * 64 * PITCH)  // 4608 words
#define NSTEP (IN_CH / 8)            // 75

__global__ __launch_bounds__(128) void k_gemm_mma(const float* __restrict__ x,
                                                  const int* __restrict__ tptr) {
    int k = blockIdx.z;
    if (k > *tptr) return;
    int b0 = blockIdx.x * 128;
    int g0 = blockIdx.y * 64;

    __shared__ uint32_t S[2 * BUFW];  // 36 KB

    int tid = threadIdx.x;
    int wid = tid >> 5, lane = tid & 31;
    int mw = wid & 1, nw = wid >> 1;
    int g = lane >> 2, tg = lane & 3;

    // Global tile-load addressing (per-thread constant)
    const float* ax = x + ((size_t)(b0 + tid) * ADAPTERS + k) * IN_CH;
    int brow = tid >> 1, bcoff = (tid & 1) * 4;
    int gn = g0 + brow;
    bool bval = gn < NFUSED;
    int nr = bval ? (gn / CLASS_DIM) : 0;
    int dr = bval ? (gn - nr * CLASS_DIM) : 0;
    const float* bx = g_BT + ((size_t)(k * CAPS + nr) * CLASS_DIM + dr) * IN_CH + bcoff;

    float acc[4][4][4];
#pragma unroll
    for (int i = 0; i < 4; i++)
#pragma unroll
        for (int j = 0; j < 4; j++)
#pragma unroll
            for (int q = 0; q < 4; q++) acc[i][j][q] = 0.f;

    // Prologue: load k-step 0
    float4 va0 = *reinterpret_cast<const float4*>(ax);
    float4 va1 = *reinterpret_cast<const float4*>(ax + 4);
    float4 vb = make_float4(0.f, 0.f, 0.f, 0.f);
    if (bval) vb = *reinterpret_cast<const float4*>(bx);

#define CVT_ST(base_hi, base_lo, idx, v) do { \
    uint32_t _h = tf32_rna(v); \
    float _lf = (v) - __uint_as_float(_h); \
    S[(base_hi) + (idx)] = _h; \
    S[(base_lo) + (idx)] = tf32_rna(_lf); \
} while (0)

    {
        int ab = 0 + AHI, al = 0 + ALO, ai = tid * PITCH;
        CVT_ST(ab, al, ai + 0, va0.x); CVT_ST(ab, al, ai + 1, va0.y);
        CVT_ST(ab, al, ai + 2, va0.z); CVT_ST(ab, al, ai + 3, va0.w);
        CVT_ST(ab, al, ai + 4, va1.x); CVT_ST(ab, al, ai + 5, va1.y);
        CVT_ST(ab, al, ai + 6, va1.z); CVT_ST(ab, al, ai + 7, va1.w);
        int bb = 0 + BHI, bl = 0 + BLO, bi = brow * PITCH + bcoff;
        CVT_ST(bb, bl, bi + 0, vb.x); CVT_ST(bb, bl, bi + 1, vb.y);
        CVT_ST(bb, bl, bi + 2, vb.z); CVT_ST(bb, bl, bi + 3, vb.w);
    }

    for (int ct = 0; ct < NSTEP; ct++) {
        __syncthreads();
        bool more = (ct + 1 < NSTEP);
        if (more) {
            int c = (ct + 1) * 8;
            va0 = *reinterpret_cast<const float4*>(ax + c);
            va1 = *reinterpret_cast<const float4*>(ax + c + 4);
            if (bval) vb = *reinterpret_cast<const float4*>(bx + c);
        }

        int buf = (ct & 1) * BUFW;
        // Fragment loads (bank-conflict-free: pitch 12)
        uint32_t ah0[4], ah1[4], ah2[4], ah3[4];
        uint32_t al0[4], al1[4], al2[4], al3[4];
        uint32_t bh0[4], bh1[4], bl0[4], bl1[4];
#pragma unroll
        for (int i = 0; i < 4; i++) {
            int r = mw * 64 + i * 16 + g;
            ah0[i] = S[buf + AHI + r * PITCH + tg];
            ah1[i] = S[buf + AHI + (r + 8) * PITCH + tg];
            ah2[i] = S[buf + AHI + r * PITCH + tg + 4];
            ah3[i] = S[buf + AHI + (r + 8) * PITCH + tg + 4];
            al0[i] = S[buf + ALO + r * PITCH + tg];
            al1[i] = S[buf + ALO + (r + 8) * PITCH + tg];
            al2[i] = S[buf + ALO + r * PITCH + tg + 4];
            al3[i] = S[buf + ALO + (r + 8) * PITCH + tg + 4];
        }
#pragma unroll
        for (int j = 0; j < 4; j++) {
            int r = nw * 32 + j * 8 + g;
            bh0[j] = S[buf + BHI + r * PITCH + tg];
            bh1[j] = S[buf + BHI + r * PITCH + tg + 4];
            bl0[j] = S[buf + BLO + r * PITCH + tg];
            bl1[j] = S[buf + BLO + r * PITCH + tg + 4];
        }

#pragma unroll
        for (int i = 0; i < 4; i++)
#pragma unroll
            for (int j = 0; j < 4; j++) {
                mma_tf32(acc[i][j], ah0[i], ah1[i], ah2[i], ah3[i], bh0[j], bh1[j]);
                mma_tf32(acc[i][j], al0[i], al1[i], al2[i], al3[i], bh0[j], bh1[j]);
                mma_tf32(acc[i][j], ah0[i], ah1[i], ah2[i], ah3[i], bl0[j], bl1[j]);
            }

        if (more) {
            int nb = ((ct + 1) & 1) * BUFW;
            int ab = nb + AHI, al = nb + ALO, ai = tid * PITCH;
            CVT_ST(ab, al, ai + 0, va0.x); CVT_ST(ab, al, ai + 1, va0.y);
            CVT_ST(ab, al, ai + 2, va0.z); CVT_ST(ab, al, ai + 3, va0.w);
            CVT_ST(ab, al, ai + 4, va1.x); CVT_ST(ab, al, ai + 5, va1.y);
            CVT_ST(ab, al, ai + 6, va1.z); CVT_ST(ab, al, ai + 7, va1.w);
            int bb = nb + BHI, bl = nb + BLO, bi = brow * PITCH + bcoff;
            CVT_ST(bb, bl, bi + 0, vb.x); CVT_ST(bb, bl, bi + 1, vb.y);
            CVT_ST(bb, bl, bi + 2, vb.z); CVT_ST(bb, bl, bi + 3, vb.w);
        }
    }

    // Epilogue: c0,c1 -> row (g), c2,c3 -> row (g+8); cols tg*2, tg*2+1
#pragma unroll
    for (int j = 0; j < 4; j++) {
        int gc = g0 + nw * 32 + j * 8 + tg * 2;
        if (gc < NFUSED) {
            int n = gc / CLASS_DIM, d = gc - n * CLASS_DIM;  // pair stays in-region (gc even)
            float* p = g_P + ((size_t)(n * ADAPTERS + k) * BATCH) * CLASS_DIM + d;
#pragma unroll
            for (int i = 0; i < 4; i++) {
                int mr = b0 + mw * 64 + i * 16 + g;
                *reinterpret_cast<float2*>(p + (size_t)mr * CLASS_DIM) =
                    make_float2(acc[i][j][0], acc[i][j][1]);
                *reinterpret_cast<float2*>(p + (size_t)(mr + 8) * CLASS_DIM) =
                    make_float2(acc[i][j][2], acc[i][j][3]);
            }
        }
    }
}

// ---------------------------------------------------------------------------
// Kernel 2: dynamic routing per (n, b). Logits constant over d -> 40-vectors.
// ---------------------------------------------------------------------------
__global__ __launch_bounds__(256) void k_route(const int* __restrict__ tptr,
                                               const float* __restrict__ tsv) {
    __shared__ float Ps[ADAPTERS][CLASS_DIM];
    __shared__ float tsvv[ADAPTERS], maskv[ADAPTERS];
    __shared__ float l[ADAPTERS], probs[ADAPTERS], leff[ADAPTERS];
    __shared__ float vote[CLASS_DIM], outv[CLASS_DIM];
    __shared__ float coef_s;

    int b = blockIdx.x, n = blockIdx.y;
    int tid = threadIdx.x;
    int t = *tptr;

    const float* Pb = g_P + ((size_t)(n * ADAPTERS) * BATCH + b) * CLASS_DIM;
    for (int idx = tid; idx < ADAPTERS * CLASS_DIM; idx += 256) {
        int k = idx / CLASS_DIM, d = idx - k * CLASS_DIM;
        Ps[k][d] = Pb[(size_t)k * BATCH * CLASS_DIM + d];
    }
    if (tid < ADAPTERS) {
        float tv = tsv[t * ADAPTERS + tid];
        tsvv[tid] = tv;
        maskv[tid] = (tv == 0.f) ? -10000.f : 0.f;
        l[tid] = 0.f;
    }
    __syncthreads();

    for (int it = 0; it < 3; it++) {
        if (tid < ADAPTERS) leff[tid] = l[tid] * tsvv[tid] + maskv[tid];
        __syncthreads();
        if (tid == 0) {
            float mx = leff[0];
            for (int kk = 1; kk < ADAPTERS; kk++) mx = fmaxf(mx, leff[kk]);
            float sm = 0.f;
            for (int kk = 0; kk < ADAPTERS; kk++) {
                float e = expf(leff[kk] - mx);
                probs[kk] = e;
                sm += e;
            }
            float inv = 1.f / sm;
            for (int kk = 0; kk < ADAPTERS; kk++) probs[kk] *= inv;
        }
        __syncthreads();
        if (tid < CLASS_DIM) {
            float v = 0.f;
#pragma unroll 8
            for (int kk = 0; kk < ADAPTERS; kk++) v += probs[kk] * Ps[kk][tid];
            vote[tid] = v;
        }
        __syncthreads();
        if (it == 2) break;

        if (tid < 32) {
            float p = 0.f;
            for (int d = tid; d < CLASS_DIM; d += 32) {
                float v = vote[d];
                p += v * v;
            }
            for (int o = 16; o > 0; o >>= 1) p += __shfl_down_sync(0xffffffff, p, o);
            if (tid == 0) {
                float sq = p;
                coef_s = sqrtf(sq) / (1.f + sq);
            }
        }
        __syncthreads();
        if (tid < CLASS_DIM) outv[tid] = vote[tid] * coef_s;
        __syncthreads();

        int w = tid >> 5, lane = tid & 31;
        for (int kk = w; kk < ADAPTERS; kk += 8) {
            float p = 0.f;
            for (int d = lane; d < CLASS_DIM; d += 32) p += Ps[kk][d] * outv[d];
            for (int o = 16; o > 0; o >>= 1) p += __shfl_down_sync(0xffffffff, p, o);
            if (lane == 0) l[kk] += p;
        }
        __syncthreads();
    }

    if (tid < CLASS_DIM) g_V[((size_t)n * BATCH + b) * CLASS_DIM + tid] = vote[tid];
}

// ---------------------------------------------------------------------------
// Kernel 3: expansion. Register-resident gated coefficients; streaming stores.
// ---------------------------------------------------------------------------
#define EXP_SPLIT 8
#define EXP_ROWS (CLASS_DIM / EXP_SPLIT)  // 25

__global__ __launch_bounds__(192) void k_expand(const int* __restrict__ tptr,
                                                const float* __restrict__ s_ptr,
                                                const float* __restrict__ W,
                                                const float* __restrict__ bvec,
                                                const float* __restrict__ el,
                                                float* __restrict__ out) {
    __shared__ float h[CLASS_DIM * CAPS];

    int b2 = blockIdx.x;
    int d2_0 = blockIdx.y * EXP_ROWS;
    int tid = threadIdx.x;
    int t = *tptr;
    float s = s_ptr[0];

    for (int idx = tid; idx < CLASS_DIM * CAPS; idx += 192)
        h[idx] = g_V[(size_t)b2 * (CLASS_DIM * CAPS) + idx];

    int j = tid * 4;
    float4 e4 = *reinterpret_cast<const float4*>(el + (size_t)t * DHID + j);
    float4 b4 = *reinterpret_cast<const float4*>(bvec + j);
    float g0 = 1.f / (1.f + expf(-s * e4.x));
    float g1 = 1.f / (1.f + expf(-s * e4.y));
    float g2 = 1.f / (1.f + expf(-s * e4.z));
    float g3 = 1.f / (1.f + expf(-s * e4.w));
    float4 w0 = *reinterpret_cast<const float4*>(W + j * 3);
    float4 w1 = *reinterpret_cast<const float4*>(W + j * 3 + 4);
    float4 w2 = *reinterpret_cast<const float4*>(W + j * 3 + 8);
    float4 c0 = make_float4(w0.x * g0, w0.y * g0, w0.z * g0, b4.x * g0);
    float4 c1 = make_float4(w0.w * g1, w1.x * g1, w1.y * g1, b4.y * g1);
    float4 c2 = make_float4(w1.z * g2, w1.w * g2, w2.x * g2, b4.z * g2);
    float4 c3 = make_float4(w2.y * g3, w2.z * g3, w2.w * g3, b4.w * g3);
    __syncthreads();

    float* ob = out + (size_t)b2 * CLASS_DIM * DHID + (size_t)d2_0 * DHID + j;
    const float* hp = h + d2_0 * 3;
#pragma unroll 5
    for (int r = 0; r < EXP_ROWS; r++) {
        float h0 = hp[0], h1 = hp[1], h2 = hp[2];
        hp += 3;
        float4 o;
        o.x = fmaf(h0, c0.x, fmaf(h1, c0.y, fmaf(h2, c0.z, c0.w)));
        o.y = fmaf(h0, c1.x, fmaf(h1, c1.y, fmaf(h2, c1.z, c1.w)));
        o.z = fmaf(h0, c2.x, fmaf(h1, c2.y, fmaf(h2, c2.z, c2.w)));
        o.w = fmaf(h0, c3.x, fmaf(h1, c3.y, fmaf(h2, c3.z, c3.w)));
        __stcs(reinterpret_cast<float4*>(ob), o);
        ob += DHID;
    }
}

// ---------------------------------------------------------------------------
extern "C" void kernel_launch(void* const* d_in, const int* in_sizes, int n_in,
                              void* d_out, int out_size) {
    const int* t = (const int*)d_in[0];
    const float* x = (const float*)d_in[1];
    const float* s = (const float*)d_in[2];
    const float* rw = (const float*)d_in[3];
    const float* W = (const float*)d_in[4];
    const float* bb = (const float*)d_in[5];
    const float* el = (const float*)d_in[6];
    const float* tsv = (const float*)d_in[7];
    float* out = (float*)d_out;

    k_btrans<<<dim3(ADAPTERS * CAPS, (IN_CH + 31) / 32, (CLASS_DIM + 31) / 32), dim3(32, 8)>>>(rw, t);
    k_gemm_mma<<<dim3(2, (NFUSED + 63) / 64, ADAPTERS), 128>>>(x, t);
    k_route<<<dim3(BATCH, CAPS), 256>>>(t, tsv);
    k_expand<<<dim3(BATCH, EXP_SPLIT), 192>>>(t, s, W, bb, el, out);
}

// round 9
// speedup vs baseline: 1.1621x; 1.1621x over previous
#include <cuda_runtime.h>
#include <math.h>
#include <cstdint>

#define ADAPTERS 40
#define CAPS 3
#define CLASS_DIM 200
#define IN_CH 600
#define BATCH 256
#define DHID 768
#define NFUSED (CAPS * CLASS_DIM)  // 600

// Scratch (static device arrays -- no allocation at runtime)
__device__ float g_Ahi[ADAPTERS * BATCH * IN_CH];            // [k][b][c]
__device__ float g_Alo[ADAPTERS * BATCH * IN_CH];
__device__ float g_Bhi[ADAPTERS * CAPS * CLASS_DIM * IN_CH]; // [kn][d][c]
__device__ float g_Blo[ADAPTERS * CAPS * CLASS_DIM * IN_CH];
__device__ float g_P[CAPS * ADAPTERS * BATCH * CLASS_DIM];   // [n][k][b][d]
__device__ float g_V[CAPS * BATCH * CLASS_DIM];              // [n][b][d] flat

// ---------------------------------------------------------------------------
// tf32 split helpers: mask-based (integer AND -- cannot be optimized away,
// unlike cvt.rna.tf32 which proved to be an identity on this toolchain)
// ---------------------------------------------------------------------------
__device__ __forceinline__ float tf32_hi(float v) {
    return __uint_as_float(__float_as_uint(v) & 0xFFFFE000u);
}
__device__ __forceinline__ void mma_tf32(float* c, const uint32_t a0, const uint32_t a1,
                                         const uint32_t a2, const uint32_t a3,
                                         const uint32_t b0, const uint32_t b1) {
    asm volatile(
        "mma.sync.aligned.m16n8k8.row.col.f32.tf32.tf32.f32 "
        "{%0,%1,%2,%3}, {%4,%5,%6,%7}, {%8,%9}, {%0,%1,%2,%3};"
        : "+f"(c[0]), "+f"(c[1]), "+f"(c[2]), "+f"(c[3])
        : "r"(a0), "r"(a1), "r"(a2), "r"(a3), "r"(b0), "r"(b1));
}

// ---------------------------------------------------------------------------
// Kernel 0a: A prep: x (b,k,c) -> hi/lo planes [k][b][c]
// ---------------------------------------------------------------------------
__global__ void k_aprep(const float* __restrict__ x, const int* __restrict__ tptr) {
    int k = blockIdx.x;
    if (k > *tptr) return;
    int b = blockIdx.y;
    const float* src = x + ((size_t)b * ADAPTERS + k) * IN_CH;
    float* dh = g_Ahi + ((size_t)k * BATCH + b) * IN_CH;
    float* dl = g_Alo + ((size_t)k * BATCH + b) * IN_CH;
    for (int i = threadIdx.x; i < IN_CH / 4; i += 128) {
        float4 v = *reinterpret_cast<const float4*>(src + i * 4);
        float4 h, l;
        h.x = tf32_hi(v.x); h.y = tf32_hi(v.y); h.z = tf32_hi(v.z); h.w = tf32_hi(v.w);
        l.x = v.x - h.x; l.y = v.y - h.y; l.z = v.z - h.z; l.w = v.w - h.w;
        *reinterpret_cast<float4*>(dh + i * 4) = h;
        *reinterpret_cast<float4*>(dl + i * 4) = l;
    }
}

// ---------------------------------------------------------------------------
// Kernel 0b: B prep: rw[kn] (600c x 200d) -> transposed hi/lo planes [kn][d][c]
// ---------------------------------------------------------------------------
__global__ void k_bprep(const float* __restrict__ rw, const int* __restrict__ tptr) {
    int kn = blockIdx.x;
    if (kn / 3 > *tptr) return;
    __shared__ float tile[32][33];
    int c0 = blockIdx.y * 32, d0 = blockIdx.z * 32;
    int tx = threadIdx.x, ty = threadIdx.y;  // (32,8)
#pragma unroll
    for (int i = 0; i < 4; i++) {
        int c = c0 + ty + i * 8, d = d0 + tx;
        float v = 0.f;
        if (c < IN_CH && d < CLASS_DIM) v = rw[((size_t)kn * IN_CH + c) * CLASS_DIM + d];
        tile[ty + i * 8][tx] = v;
    }
    __syncthreads();
#pragma unroll
    for (int i = 0; i < 4; i++) {
        int d = d0 + ty + i * 8, c = c0 + tx;
        if (d < CLASS_DIM && c < IN_CH) {
            float v = tile[tx][ty + i * 8];
            float h = tf32_hi(v);
            size_t idx = ((size_t)kn * CLASS_DIM + d) * IN_CH + c;
            g_Bhi[idx] = h;
            g_Blo[idx] = v - h;
        }
    }
}

// ---------------------------------------------------------------------------
// Kernel 1: priors GEMM: mma.sync m16n8k8 tf32, 3-term masked split, fp32
// accumulate. Per CTA (k<=t, mhalf, n-block): C[128x64] = A[128x600] B[600x64]
// 75 K-steps. 4 warps (2m x 2n), warp tile 64x32. Smem pitch 12 words ->
// conflict-free (proven R8). Hot loop: pure LDG/STS/LDS/HMMA, no conversion.
// ---------------------------------------------------------------------------
#define PITCH 12
#define AHI 0
#define ALO (128 * PITCH)
#define BHI (2 * 128 * PITCH)
#define BLO (2 * 128 * PITCH + 64 * PITCH)
#define BUFW (2 * 128 * PITCH + 2 * 64 * PITCH)  // 4608 words
#define NSTEP (IN_CH / 8)  // 75

__global__ __launch_bounds__(128) void k_gemm_mma(const int* __restrict__ tptr) {
    int k = blockIdx.z;
    if (k > *tptr) return;
    int b0 = blockIdx.x * 128;
    int g0 = blockIdx.y * 64;

    __shared__ uint32_t S[2 * BUFW];  // 36 KB

    int tid = threadIdx.x;
    int wid = tid >> 5, lane = tid & 31;
    int mw = wid & 1, nw = wid >> 1;
    int g = lane >> 2, tg = lane & 3;

    const float* axh = g_Ahi + ((size_t)k * BATCH + b0 + tid) * IN_CH;
    const float* axl = g_Alo + ((size_t)k * BATCH + b0 + tid) * IN_CH;
    int brow = tid >> 1, bcoff = (tid & 1) * 4;
    int gn = g0 + brow;
    bool bval = gn < NFUSED;
    int nr = bval ? (gn / CLASS_DIM) : 0;
    int dr = bval ? (gn - nr * CLASS_DIM) : 0;
    size_t boff = ((size_t)(k * CAPS + nr) * CLASS_DIM + dr) * IN_CH + bcoff;
    const float* bxh = g_Bhi + boff;
    const float* bxl = g_Blo + boff;

    float acc[4][4][4];
#pragma unroll
    for (int i = 0; i < 4; i++)
#pragma unroll
        for (int j = 0; j < 4; j++)
#pragma unroll
            for (int q = 0; q < 4; q++) acc[i][j][q] = 0.f;

    // Prologue: load k-step 0
    uint4 vah0 = *reinterpret_cast<const uint4*>(axh);
    uint4 vah1 = *reinterpret_cast<const uint4*>(axh + 4);
    uint4 val0 = *reinterpret_cast<const uint4*>(axl);
    uint4 val1 = *reinterpret_cast<const uint4*>(axl + 4);
    uint4 vbh = make_uint4(0, 0, 0, 0), vbl = make_uint4(0, 0, 0, 0);
    if (bval) {
        vbh = *reinterpret_cast<const uint4*>(bxh);
        vbl = *reinterpret_cast<const uint4*>(bxl);
    }

    // stage into buffer 0
    {
        int ai = tid * PITCH, bi = brow * PITCH + bcoff;
        *reinterpret_cast<uint4*>(&S[AHI + ai]) = vah0;
        *reinterpret_cast<uint4*>(&S[AHI + ai + 4]) = vah1;
        *reinterpret_cast<uint4*>(&S[ALO + ai]) = val0;
        *reinterpret_cast<uint4*>(&S[ALO + ai + 4]) = val1;
        *reinterpret_cast<uint4*>(&S[BHI + bi]) = vbh;
        *reinterpret_cast<uint4*>(&S[BLO + bi]) = vbl;
    }

    for (int ct = 0; ct < NSTEP; ct++) {
        __syncthreads();
        bool more = (ct + 1 < NSTEP);
        if (more) {
            int c = (ct + 1) * 8;
            vah0 = *reinterpret_cast<const uint4*>(axh + c);
            vah1 = *reinterpret_cast<const uint4*>(axh + c + 4);
            val0 = *reinterpret_cast<const uint4*>(axl + c);
            val1 = *reinterpret_cast<const uint4*>(axl + c + 4);
            if (bval) {
                vbh = *reinterpret_cast<const uint4*>(bxh + c);
                vbl = *reinterpret_cast<const uint4*>(bxl + c);
            }
        }

        int buf = (ct & 1) * BUFW;
        uint32_t ah0[4], ah1[4], ah2[4], ah3[4];
        uint32_t al0[4], al1[4], al2[4], al3[4];
        uint32_t bh0[4], bh1[4], bl0[4], bl1[4];
#pragma unroll
        for (int i = 0; i < 4; i++) {
            int r = mw * 64 + i * 16 + g;
            ah0[i] = S[buf + AHI + r * PITCH + tg];
            ah1[i] = S[buf + AHI + (r + 8) * PITCH + tg];
            ah2[i] = S[buf + AHI + r * PITCH + tg + 4];
            ah3[i] = S[buf + AHI + (r + 8) * PITCH + tg + 4];
            al0[i] = S[buf + ALO + r * PITCH + tg];
            al1[i] = S[buf + ALO + (r + 8) * PITCH + tg];
            al2[i] = S[buf + ALO + r * PITCH + tg + 4];
            al3[i] = S[buf + ALO + (r + 8) * PITCH + tg + 4];
        }
#pragma unroll
        for (int j = 0; j < 4; j++) {
            int r = nw * 32 + j * 8 + g;
            bh0[j] = S[buf + BHI + r * PITCH + tg];
            bh1[j] = S[buf + BHI + r * PITCH + tg + 4];
            bl0[j] = S[buf + BLO + r * PITCH + tg];
            bl1[j] = S[buf + BLO + r * PITCH + tg + 4];
        }

#pragma unroll
        for (int i = 0; i < 4; i++)
#pragma unroll
            for (int j = 0; j < 4; j++) {
                mma_tf32(acc[i][j], ah0[i], ah1[i], ah2[i], ah3[i], bh0[j], bh1[j]);
                mma_tf32(acc[i][j], al0[i], al1[i], al2[i], al3[i], bh0[j], bh1[j]);
                mma_tf32(acc[i][j], ah0[i], ah1[i], ah2[i], ah3[i], bl0[j], bl1[j]);
            }

        if (more) {
            int nb = ((ct + 1) & 1) * BUFW;
            int ai = tid * PITCH, bi = brow * PITCH + bcoff;
            *reinterpret_cast<uint4*>(&S[nb + AHI + ai]) = vah0;
            *reinterpret_cast<uint4*>(&S[nb + AHI + ai + 4]) = vah1;
            *reinterpret_cast<uint4*>(&S[nb + ALO + ai]) = val0;
            *reinterpret_cast<uint4*>(&S[nb + ALO + ai + 4]) = val1;
            *reinterpret_cast<uint4*>(&S[nb + BHI + bi]) = vbh;
            *reinterpret_cast<uint4*>(&S[nb + BLO + bi]) = vbl;
        }
    }

    // Epilogue: c0,c1 -> row g; c2,c3 -> row g+8; cols tg*2, tg*2+1
#pragma unroll
    for (int j = 0; j < 4; j++) {
        int gc = g0 + nw * 32 + j * 8 + tg * 2;
        if (gc < NFUSED) {
            int n = gc / CLASS_DIM, d = gc - n * CLASS_DIM;  // gc even -> pair in-region
            float* p = g_P + ((size_t)(n * ADAPTERS + k) * BATCH) * CLASS_DIM + d;
#pragma unroll
            for (int i = 0; i < 4; i++) {
                int mr = b0 + mw * 64 + i * 16 + g;
                *reinterpret_cast<float2*>(p + (size_t)mr * CLASS_DIM) =
                    make_float2(acc[i][j][0], acc[i][j][1]);
                *reinterpret_cast<float2*>(p + (size_t)(mr + 8) * CLASS_DIM) =
                    make_float2(acc[i][j][2], acc[i][j][3]);
            }
        }
    }
}

// ---------------------------------------------------------------------------
// Kernel 2: dynamic routing per (n, b). Logits constant over d -> 40-vectors.
// ---------------------------------------------------------------------------
__global__ __launch_bounds__(256) void k_route(const int* __restrict__ tptr,
                                               const float* __restrict__ tsv) {
    __shared__ float Ps[ADAPTERS][CLASS_DIM];
    __shared__ float tsvv[ADAPTERS], maskv[ADAPTERS];
    __shared__ float l[ADAPTERS], probs[ADAPTERS], leff[ADAPTERS];
    __shared__ float vote[CLASS_DIM], outv[CLASS_DIM];
    __shared__ float coef_s;

    int b = blockIdx.x, n = blockIdx.y;
    int tid = threadIdx.x;
    int t = *tptr;

    const float* Pb = g_P + ((size_t)(n * ADAPTERS) * BATCH + b) * CLASS_DIM;
    for (int idx = tid; idx < ADAPTERS * CLASS_DIM; idx += 256) {
        int k = idx / CLASS_DIM, d = idx - k * CLASS_DIM;
        Ps[k][d] = Pb[(size_t)k * BATCH * CLASS_DIM + d];
    }
    if (tid < ADAPTERS) {
        float tv = tsv[t * ADAPTERS + tid];
        tsvv[tid] = tv;
        maskv[tid] = (tv == 0.f) ? -10000.f : 0.f;
        l[tid] = 0.f;
    }
    __syncthreads();

    for (int it = 0; it < 3; it++) {
        if (tid < ADAPTERS) leff[tid] = l[tid] * tsvv[tid] + maskv[tid];
        __syncthreads();
        if (tid == 0) {
            float mx = leff[0];
            for (int kk = 1; kk < ADAPTERS; kk++) mx = fmaxf(mx, leff[kk]);
            float sm = 0.f;
            for (int kk = 0; kk < ADAPTERS; kk++) {
                float e = expf(leff[kk] - mx);
                probs[kk] = e;
                sm += e;
            }
            float inv = 1.f / sm;
            for (int kk = 0; kk < ADAPTERS; kk++) probs[kk] *= inv;
        }
        __syncthreads();
        if (tid < CLASS_DIM) {
            float v = 0.f;
#pragma unroll 8
            for (int kk = 0; kk < ADAPTERS; kk++) v += probs[kk] * Ps[kk][tid];
            vote[tid] = v;
        }
        __syncthreads();
        if (it == 2) break;

        if (tid < 32) {
            float p = 0.f;
            for (int d = tid; d < CLASS_DIM; d += 32) {
                float v = vote[d];
                p += v * v;
            }
            for (int o = 16; o > 0; o >>= 1) p += __shfl_down_sync(0xffffffff, p, o);
            if (tid == 0) {
                float sq = p;
                coef_s = sqrtf(sq) / (1.f + sq);
            }
        }
        __syncthreads();
        if (tid < CLASS_DIM) outv[tid] = vote[tid] * coef_s;
        __syncthreads();

        int w = tid >> 5, lane = tid & 31;
        for (int kk = w; kk < ADAPTERS; kk += 8) {
            float p = 0.f;
            for (int d = lane; d < CLASS_DIM; d += 32) p += Ps[kk][d] * outv[d];
            for (int o = 16; o > 0; o >>= 1) p += __shfl_down_sync(0xffffffff, p, o);
            if (lane == 0) l[kk] += p;
        }
        __syncthreads();
    }

    if (tid < CLASS_DIM) g_V[((size_t)n * BATCH + b) * CLASS_DIM + tid] = vote[tid];
}

// ---------------------------------------------------------------------------
// Kernel 3: expansion. Register-resident gated coefficients; streaming stores.
// ---------------------------------------------------------------------------
#define EXP_SPLIT 8
#define EXP_ROWS (CLASS_DIM / EXP_SPLIT)  // 25

__global__ __launch_bounds__(192) void k_expand(const int* __restrict__ tptr,
                                                const float* __restrict__ s_ptr,
                                                const float* __restrict__ W,
                                                const float* __restrict__ bvec,
                                                const float* __restrict__ el,
                                                float* __restrict__ out) {
    __shared__ float h[CLASS_DIM * CAPS];

    int b2 = blockIdx.x;
    int d2_0 = blockIdx.y * EXP_ROWS;
    int tid = threadIdx.x;
    int t = *tptr;
    float s = s_ptr[0];

    for (int idx = tid; idx < CLASS_DIM * CAPS; idx += 192)
        h[idx] = g_V[(size_t)b2 * (CLASS_DIM * CAPS) + idx];

    int j = tid * 4;
    float4 e4 = *reinterpret_cast<const float4*>(el + (size_t)t * DHID + j);
    float4 b4 = *reinterpret_cast<const float4*>(bvec + j);
    float g0 = 1.f / (1.f + expf(-s * e4.x));
    float g1 = 1.f / (1.f + expf(-s * e4.y));
    float g2 = 1.f / (1.f + expf(-s * e4.z));
    float g3 = 1.f / (1.f + expf(-s * e4.w));
    float4 w0 = *reinterpret_cast<const float4*>(W + j * 3);
    float4 w1 = *reinterpret_cast<const float4*>(W + j * 3 + 4);
    float4 w2 = *reinterpret_cast<const float4*>(W + j * 3 + 8);
    float4 c0 = make_float4(w0.x * g0, w0.y * g0, w0.z * g0, b4.x * g0);
    float4 c1 = make_float4(w0.w * g1, w1.x * g1, w1.y * g1, b4.y * g1);
    float4 c2 = make_float4(w1.z * g2, w1.w * g2, w2.x * g2, b4.z * g2);
    float4 c3 = make_float4(w2.y * g3, w2.z * g3, w2.w * g3, b4.w * g3);
    __syncthreads();

    float* ob = out + (size_t)b2 * CLASS_DIM * DHID + (size_t)d2_0 * DHID + j;
    const float* hp = h + d2_0 * 3;
#pragma unroll 5
    for (int r = 0; r < EXP_ROWS; r++) {
        float h0 = hp[0], h1 = hp[1], h2 = hp[2];
        hp += 3;
        float4 o;
        o.x = fmaf(h0, c0.x, fmaf(h1, c0.y, fmaf(h2, c0.z, c0.w)));
        o.y = fmaf(h0, c1.x, fmaf(h1, c1.y, fmaf(h2, c1.z, c1.w)));
        o.z = fmaf(h0, c2.x, fmaf(h1, c2.y, fmaf(h2, c2.z, c2.w)));
        o.w = fmaf(h0, c3.x, fmaf(h1, c3.y, fmaf(h2, c3.z, c3.w)));
        __stcs(reinterpret_cast<float4*>(ob), o);
        ob += DHID;
    }
}

// ---------------------------------------------------------------------------
extern "C" void kernel_launch(void* const* d_in, const int* in_sizes, int n_in,
                              void* d_out, int out_size) {
    const int* t = (const int*)d_in[0];
    const float* x = (const float*)d_in[1];
    const float* s = (const float*)d_in[2];
    const float* rw = (const float*)d_in[3];
    const float* W = (const float*)d_in[4];
    const float* bb = (const float*)d_in[5];
    const float* el = (const float*)d_in[6];
    const float* tsv = (const float*)d_in[7];
    float* out = (float*)d_out;

    k_aprep<<<dim3(ADAPTERS, BATCH), 128>>>(x, t);
    k_bprep<<<dim3(ADAPTERS * CAPS, (IN_CH + 31) / 32, (CLASS_DIM + 31) / 32), dim3(32, 8)>>>(rw, t);
    k_gemm_mma<<<dim3(2, (NFUSED + 63) / 64, ADAPTERS), 128>>>(t);
    k_route<<<dim3(BATCH, CAPS), 256>>>(t, tsv);
    k_expand<<<dim3(BATCH, EXP_SPLIT), 192>>>(t, s, W, bb, el, out);
}

// round 10
// speedup vs baseline: 1.3099x; 1.1271x over previous
#include <cuda_runtime.h>
#include <math.h>

#define ADAPTERS 40
#define CAPS 3
#define CLASS_DIM 200
#define IN_CH 600
#define BATCH 256
#define DHID 768
#define NFUSED (CAPS * CLASS_DIM)  // 600

// Scratch (static device arrays -- no allocation at runtime)
__device__ float g_xT[ADAPTERS * IN_CH * BATCH];           // [k][c][b]
__device__ float g_P[CAPS * ADAPTERS * BATCH * CLASS_DIM]; // [n][k][b][d]
__device__ float g_V[CAPS * BATCH * CLASS_DIM];            // [n][b][d] flat

// ---------------------------------------------------------------------------
// f32x2 packed-FMA helpers
// ---------------------------------------------------------------------------
__device__ __forceinline__ unsigned long long pk2(float lo, float hi) {
    unsigned long long r;
    asm("mov.b64 %0, {%1, %2};" : "=l"(r) : "f"(lo), "f"(hi));
    return r;
}
__device__ __forceinline__ void ffma2(unsigned long long& c, unsigned long long a, unsigned long long b) {
    asm("fma.rn.f32x2 %0, %1, %2, %0;" : "+l"(c) : "l"(a), "l"(b));
}
__device__ __forceinline__ void unpk2(unsigned long long v, float& lo, float& hi) {
    asm("mov.b64 {%0, %1}, %2;" : "=f"(lo), "=f"(hi) : "l"(v));
}

// ---------------------------------------------------------------------------
// Kernel 0: transpose x (b,k,c) -> xT (k,c,b); only k<=t slices are consumed
// ---------------------------------------------------------------------------
__global__ void k_transpose(const float* __restrict__ x, const int* __restrict__ tptr) {
    int k = blockIdx.x;
    if (k > *tptr) return;
    __shared__ float tile[32][33];
    int c0 = blockIdx.y * 32;
    int b0 = blockIdx.z * 32;
    int tx = threadIdx.x, ty = threadIdx.y;  // (32, 8)
#pragma unroll
    for (int i = 0; i < 4; i++) {
        int b = b0 + ty + i * 8;
        int c = c0 + tx;
        float v = 0.f;
        if (c < IN_CH) v = x[((size_t)b * ADAPTERS + k) * IN_CH + c];
        tile[ty + i * 8][tx] = v;
    }
    __syncthreads();
#pragma unroll
    for (int i = 0; i < 4; i++) {
        int c = c0 + ty + i * 8;
        int b = b0 + tx;
        if (c < IN_CH) g_xT[((size_t)k * IN_CH + c) * BATCH + b] = tile[tx][ty + i * 8];
    }
}

// ---------------------------------------------------------------------------
// Kernel 1: priors GEMM (R6 version -- 97% of fp32 roofline).
// Per k: C[256 x 600] = A[256x600] @ B[600x600] with N fusing (n,d)=n*200+d.
// BM=128, BN=64, BK=8, 128 threads, 8x8 thread tile, SPLIT 4+4 fragments
// (conflict-free LDS.128). Double-buffered smem, one __syncthreads per step.
// ---------------------------------------------------------------------------
#define BM 128
#define BN 64
#define BKK 8
#define NT (IN_CH / BKK)   // 75

__global__ __launch_bounds__(128) void k_gemm(const float* __restrict__ rw,
                                              const int* __restrict__ tptr) {
    int k = blockIdx.z;
    if (k > *tptr) return;

    int b0 = blockIdx.x * BM;
    int g0 = blockIdx.y * BN;

    __shared__ float As[2][BKK][BM];
    __shared__ float Bs[2][BKK][BN];

    int tid = threadIdx.x;
    int tn = tid & 7;
    int tm = tid >> 3;

    int arow = tid >> 5;
    int acol = (tid & 31) * 4;
    const float* Aptr = g_xT + ((size_t)k * IN_CH + arow) * BATCH + b0 + acol;

    int brow = tid >> 4;
    int bcol = (tid & 15) * 4;
    int gb = g0 + bcol;
    bool bvalid = gb < NFUSED;
    int nB = bvalid ? (gb / CLASS_DIM) : 0;
    int dB = gb - nB * CLASS_DIM;
    const float* Bptr = rw + (((size_t)(k * CAPS + nB)) * IN_CH + brow) * CLASS_DIM + dB;

    unsigned long long acc[8][4];
#pragma unroll
    for (int i = 0; i < 8; i++)
#pragma unroll
        for (int j = 0; j < 4; j++) acc[i][j] = 0ull;

    float4 a0 = *reinterpret_cast<const float4*>(Aptr);
    float4 a1 = *reinterpret_cast<const float4*>(Aptr + 4 * BATCH);
    float4 bbv = make_float4(0.f, 0.f, 0.f, 0.f);
    if (bvalid) bbv = *reinterpret_cast<const float4*>(Bptr);
    Aptr += BKK * BATCH;
    Bptr += BKK * CLASS_DIM;

    *reinterpret_cast<float4*>(&As[0][arow][acol]) = a0;
    *reinterpret_cast<float4*>(&As[0][arow + 4][acol]) = a1;
    *reinterpret_cast<float4*>(&Bs[0][brow][bcol]) = bbv;
    __syncthreads();

    int w = 0;
    for (int ct = 0; ct < NT; ct++) {
        bool more = (ct + 1 < NT);
        if (more) {
            a0 = *reinterpret_cast<const float4*>(Aptr);
            a1 = *reinterpret_cast<const float4*>(Aptr + 4 * BATCH);
            if (bvalid) bbv = *reinterpret_cast<const float4*>(Bptr);
            Aptr += BKK * BATCH;
            Bptr += BKK * CLASS_DIM;
        }

#pragma unroll
        for (int kk = 0; kk < BKK; kk++) {
            const float4 av0 = *reinterpret_cast<const float4*>(&As[w][kk][tm * 4]);
            const float4 av1 = *reinterpret_cast<const float4*>(&As[w][kk][64 + tm * 4]);
            const ulonglong2 q0 = *reinterpret_cast<const ulonglong2*>(&Bs[w][kk][tn * 4]);
            const ulonglong2 q1 = *reinterpret_cast<const ulonglong2*>(&Bs[w][kk][32 + tn * 4]);
            float am[8] = {av0.x, av0.y, av0.z, av0.w, av1.x, av1.y, av1.z, av1.w};
#pragma unroll
            for (int i = 0; i < 8; i++) {
                unsigned long long ap = pk2(am[i], am[i]);
                ffma2(acc[i][0], ap, q0.x);
                ffma2(acc[i][1], ap, q0.y);
                ffma2(acc[i][2], ap, q1.x);
                ffma2(acc[i][3], ap, q1.y);
            }
        }

        if (more) {
            int nw = w ^ 1;
            *reinterpret_cast<float4*>(&As[nw][arow][acol]) = a0;
            *reinterpret_cast<float4*>(&As[nw][arow + 4][acol]) = a1;
            *reinterpret_cast<float4*>(&Bs[nw][brow][bcol]) = bbv;
            __syncthreads();
            w = nw;
        }
    }

    int gc0 = g0 + tn * 4;
    int gc1 = g0 + 32 + tn * 4;
    if (gc0 < NFUSED) {
        int n = gc0 / CLASS_DIM, d = gc0 - n * CLASS_DIM;
        float* p = g_P + ((size_t)(n * ADAPTERS + k) * BATCH) * CLASS_DIM + d;
#pragma unroll
        for (int i = 0; i < 8; i++) {
            int m = b0 + tm * 4 + (i < 4 ? i : 60 + i);
            float4 o;
            unpk2(acc[i][0], o.x, o.y);
            unpk2(acc[i][1], o.z, o.w);
            *reinterpret_cast<float4*>(p + (size_t)m * CLASS_DIM) = o;
        }
    }
    if (gc1 < NFUSED) {
        int n = gc1 / CLASS_DIM, d = gc1 - n * CLASS_DIM;
        float* p = g_P + ((size_t)(n * ADAPTERS + k) * BATCH) * CLASS_DIM + d;
#pragma unroll
        for (int i = 0; i < 8; i++) {
            int m = b0 + tm * 4 + (i < 4 ? i : 60 + i);
            float4 o;
            unpk2(acc[i][2], o.x, o.y);
            unpk2(acc[i][3], o.z, o.w);
            *reinterpret_cast<float4*>(p + (size_t)m * CLASS_DIM) = o;
        }
    }
}

// ---------------------------------------------------------------------------
// Kernel 2: routing v2. Only k<=t rows participate (probs for k>t are exactly
// 0 via -10000 mask underflow). Parallel warp softmax; float4 smem fill;
// 21-iteration vote loops instead of 40.
// ---------------------------------------------------------------------------
__global__ __launch_bounds__(256) void k_route(const int* __restrict__ tptr,
                                               const float* __restrict__ tsv) {
    __shared__ float Ps[ADAPTERS][CLASS_DIM];
    __shared__ float tsvv[ADAPTERS], maskv[ADAPTERS];
    __shared__ float l[ADAPTERS], probs[ADAPTERS];
    __shared__ float vote[CLASS_DIM], outv[CLASS_DIM];
    __shared__ float coef_s;

    int b = blockIdx.x, n = blockIdx.y;
    int tid = threadIdx.x;
    int t = *tptr;
    int kc = t + 1;  // active adapters (k <= t)

    const float* Pb = g_P + ((size_t)(n * ADAPTERS) * BATCH + b) * CLASS_DIM;
    int nf4 = kc * (CLASS_DIM / 4);  // float4s to load
    for (int q = tid; q < nf4; q += 256) {
        int k = q / (CLASS_DIM / 4);
        int r = q - k * (CLASS_DIM / 4);
        float4 v = *reinterpret_cast<const float4*>(Pb + (size_t)k * BATCH * CLASS_DIM + r * 4);
        *reinterpret_cast<float4*>(&Ps[k][r * 4]) = v;
    }
    if (tid < ADAPTERS) {
        float tv = tsv[t * ADAPTERS + tid];
        tsvv[tid] = tv;
        maskv[tid] = (tv == 0.f) ? -10000.f : 0.f;
        l[tid] = 0.f;
    }
    __syncthreads();

    int wrp = tid >> 5, lane = tid & 31;

    for (int it = 0; it < 3; it++) {
        // Parallel softmax over k<kc (warp 0; 2 logits per lane)
        if (tid < 32) {
            float v0 = (tid < kc) ? fmaf(l[tid], tsvv[tid], maskv[tid]) : -3.0e38f;
            float v1 = (tid + 32 < kc) ? fmaf(l[tid + 32], tsvv[tid + 32], maskv[tid + 32]) : -3.0e38f;
            float mx = fmaxf(v0, v1);
#pragma unroll
            for (int o = 16; o > 0; o >>= 1) mx = fmaxf(mx, __shfl_xor_sync(0xffffffff, mx, o));
            float e0 = (tid < kc) ? expf(v0 - mx) : 0.f;
            float e1 = (tid + 32 < kc) ? expf(v1 - mx) : 0.f;
            float sm = e0 + e1;
#pragma unroll
            for (int o = 16; o > 0; o >>= 1) sm += __shfl_xor_sync(0xffffffff, sm, o);
            float inv = 1.f / sm;
            if (tid < kc) probs[tid] = e0 * inv;
            if (tid + 32 < kc) probs[tid + 32] = e1 * inv;
        }
        __syncthreads();

        if (tid < CLASS_DIM) {
            float v = 0.f;
            for (int kk = 0; kk < kc; kk++) v = fmaf(probs[kk], Ps[kk][tid], v);
            vote[tid] = v;
        }
        __syncthreads();
        if (it == 2) break;

        // squash coefficient: sqrt(sq)/(1+sq)
        if (tid < 32) {
            float p = 0.f;
            for (int d = tid; d < CLASS_DIM; d += 32) {
                float v = vote[d];
                p = fmaf(v, v, p);
            }
#pragma unroll
            for (int o = 16; o > 0; o >>= 1) p += __shfl_xor_sync(0xffffffff, p, o);
            if (tid == 0) coef_s = sqrtf(p) / (1.f + p);
        }
        __syncthreads();
        if (tid < CLASS_DIM) outv[tid] = vote[tid] * coef_s;
        __syncthreads();

        // agreement a[k] = dot(Ps[k], out) for k<kc -> l[k] += a[k]
        for (int kk = wrp; kk < kc; kk += 8) {
            float p = 0.f;
            for (int d = lane; d < CLASS_DIM; d += 32) p = fmaf(Ps[kk][d], outv[d], p);
#pragma unroll
            for (int o = 16; o > 0; o >>= 1) p += __shfl_xor_sync(0xffffffff, p, o);
            if (lane == 0) l[kk] += p;
        }
        __syncthreads();
    }

    if (tid < CLASS_DIM) g_V[((size_t)n * BATCH + b) * CLASS_DIM + tid] = vote[tid];
}

// ---------------------------------------------------------------------------
// Kernel 3: expansion. Register-resident gated coefficients; streaming stores.
// ---------------------------------------------------------------------------
#define EXP_SPLIT 8
#define EXP_ROWS (CLASS_DIM / EXP_SPLIT)  // 25

__global__ __launch_bounds__(192) void k_expand(const int* __restrict__ tptr,
                                                const float* __restrict__ s_ptr,
                                                const float* __restrict__ W,
                                                const float* __restrict__ bvec,
                                                const float* __restrict__ el,
                                                float* __restrict__ out) {
    __shared__ float h[CLASS_DIM * CAPS];

    int b2 = blockIdx.x;
    int d2_0 = blockIdx.y * EXP_ROWS;
    int tid = threadIdx.x;
    int t = *tptr;
    float s = s_ptr[0];

    for (int idx = tid; idx < CLASS_DIM * CAPS; idx += 192)
        h[idx] = g_V[(size_t)b2 * (CLASS_DIM * CAPS) + idx];

    int j = tid * 4;
    float4 e4 = *reinterpret_cast<const float4*>(el + (size_t)t * DHID + j);
    float4 b4 = *reinterpret_cast<const float4*>(bvec + j);
    float g0 = 1.f / (1.f + expf(-s * e4.x));
    float g1 = 1.f / (1.f + expf(-s * e4.y));
    float g2 = 1.f / (1.f + expf(-s * e4.z));
    float g3 = 1.f / (1.f + expf(-s * e4.w));
    float4 w0 = *reinterpret_cast<const float4*>(W + j * 3);
    float4 w1 = *reinterpret_cast<const float4*>(W + j * 3 + 4);
    float4 w2 = *reinterpret_cast<const float4*>(W + j * 3 + 8);
    float4 c0 = make_float4(w0.x * g0, w0.y * g0, w0.z * g0, b4.x * g0);
    float4 c1 = make_float4(w0.w * g1, w1.x * g1, w1.y * g1, b4.y * g1);
    float4 c2 = make_float4(w1.z * g2, w1.w * g2, w2.x * g2, b4.z * g2);
    float4 c3 = make_float4(w2.y * g3, w2.z * g3, w2.w * g3, b4.w * g3);
    __syncthreads();

    float* ob = out + (size_t)b2 * CLASS_DIM * DHID + (size_t)d2_0 * DHID + j;
    const float* hp = h + d2_0 * 3;
#pragma unroll 5
    for (int r = 0; r < EXP_ROWS; r++) {
        float h0 = hp[0], h1 = hp[1], h2 = hp[2];
        hp += 3;
        float4 o;
        o.x = fmaf(h0, c0.x, fmaf(h1, c0.y, fmaf(h2, c0.z, c0.w)));
        o.y = fmaf(h0, c1.x, fmaf(h1, c1.y, fmaf(h2, c1.z, c1.w)));
        o.z = fmaf(h0, c2.x, fmaf(h1, c2.y, fmaf(h2, c2.z, c2.w)));
        o.w = fmaf(h0, c3.x, fmaf(h1, c3.y, fmaf(h2, c3.z, c3.w)));
        __stcs(reinterpret_cast<float4*>(ob), o);
        ob += DHID;
    }
}

// ---------------------------------------------------------------------------
extern "C" void kernel_launch(void* const* d_in, const int* in_sizes, int n_in,
                              void* d_out, int out_size) {
    const int* t = (const int*)d_in[0];
    const float* x = (const float*)d_in[1];
    const float* s = (const float*)d_in[2];
    const float* rw = (const float*)d_in[3];
    const float* W = (const float*)d_in[4];
    const float* bb = (const float*)d_in[5];
    const float* el = (const float*)d_in[6];
    const float* tsv = (const float*)d_in[7];
    float* out = (float*)d_out;

    k_transpose<<<dim3(ADAPTERS, (IN_CH + 31) / 32, BATCH / 32), dim3(32, 8)>>>(x, t);
    k_gemm<<<dim3(BATCH / BM, (NFUSED + BN - 1) / BN, ADAPTERS), 128>>>(rw, t);
    k_route<<<dim3(BATCH, CAPS), 256>>>(t, tsv);
    k_expand<<<dim3(BATCH, EXP_SPLIT), 192>>>(t, s, W, bb, el, out);
}

// round 12
// speedup vs baseline: 1.8460x; 1.4093x over previous
#include <cuda_runtime.h>
#include <math.h>
#include <cstdint>

#define ADAPTERS 40
#define CAPS 3
#define CLASS_DIM 200
#define IN_CH 600
#define BATCH 256
#define DHID 768
#define NFUSED (CAPS * CLASS_DIM)  // 600

// Scratch (static device arrays -- no allocation at runtime)
__device__ float g_xT[ADAPTERS * IN_CH * BATCH];             // [k][c][b], tf32-rounded
__device__ float g_BT[ADAPTERS * CAPS * CLASS_DIM * IN_CH];  // [kn][d][c], tf32-rounded
__device__ float g_P[CAPS * ADAPTERS * BATCH * CLASS_DIM];   // [n][k][b][d]
__device__ float g_V[CAPS * BATCH * CLASS_DIM];              // [n][b][d] flat

// ---------------------------------------------------------------------------
// Software RNE rounding to tf32 bit pattern (low 13 mantissa bits zero).
// Pure integer ops -- cannot be folded away by the compiler. The sm_103
// mma.sync tf32 fallback REQUIRES tf32-clean inputs (R11 evidence: raw fp32
// bits -> 3.5e-2 error; pre-cleaned inputs (R8/R9) -> ~5e-4 floor).
// ---------------------------------------------------------------------------
__device__ __forceinline__ float tf32_rne(float v) {
    uint32_t u = __float_as_uint(v);
    uint32_t r = (u + 0xFFFu + ((u >> 13) & 1u)) & 0xFFFFE000u;
    return __uint_as_float(r);
}

__device__ __forceinline__ void mma_tf32(float* c, const uint32_t a0, const uint32_t a1,
                                         const uint32_t a2, const uint32_t a3,
                                         const uint32_t b0, const uint32_t b1) {
    asm volatile(
        "mma.sync.aligned.m16n8k8.row.col.f32.tf32.tf32.f32 "
        "{%0,%1,%2,%3}, {%4,%5,%6,%7}, {%8,%9}, {%0,%1,%2,%3};"
        : "+f"(c[0]), "+f"(c[1]), "+f"(c[2]), "+f"(c[3])
        : "r"(a0), "r"(a1), "r"(a2), "r"(a3), "r"(b0), "r"(b1));
}

// ---------------------------------------------------------------------------
// Kernel 0a: transpose x (b,k,c) -> xT (k,c,b), tf32-rounded on the way out
// ---------------------------------------------------------------------------
__global__ void k_transpose(const float* __restrict__ x, const int* __restrict__ tptr) {
    int k = blockIdx.x;
    if (k > *tptr) return;
    __shared__ float tile[32][33];
    int c0 = blockIdx.y * 32;
    int b0 = blockIdx.z * 32;
    int tx = threadIdx.x, ty = threadIdx.y;  // (32, 8)
#pragma unroll
    for (int i = 0; i < 4; i++) {
        int b = b0 + ty + i * 8;
        int c = c0 + tx;
        float v = 0.f;
        if (c < IN_CH) v = x[((size_t)b * ADAPTERS + k) * IN_CH + c];
        tile[ty + i * 8][tx] = v;
    }
    __syncthreads();
#pragma unroll
    for (int i = 0; i < 4; i++) {
        int c = c0 + ty + i * 8;
        int b = b0 + tx;
        if (c < IN_CH)
            g_xT[((size_t)k * IN_CH + c) * BATCH + b] = tf32_rne(tile[tx][ty + i * 8]);
    }
}

// ---------------------------------------------------------------------------
// Kernel 0b: B transpose: rw[kn] (600c x 200d) -> g_BT[kn] (200d x 600c),
// tf32-rounded on the way out
// ---------------------------------------------------------------------------
__global__ void k_btrans(const float* __restrict__ rw, const int* __restrict__ tptr) {
    int kn = blockIdx.x;
    if (kn / 3 > *tptr) return;
    __shared__ float tile[32][33];
    int c0 = blockIdx.y * 32, d0 = blockIdx.z * 32;
    int tx = threadIdx.x, ty = threadIdx.y;  // (32,8)
#pragma unroll
    for (int i = 0; i < 4; i++) {
        int c = c0 + ty + i * 8, d = d0 + tx;
        float v = 0.f;
        if (c < IN_CH && d < CLASS_DIM) v = rw[((size_t)kn * IN_CH + c) * CLASS_DIM + d];
        tile[ty + i * 8][tx] = v;
    }
    __syncthreads();
#pragma unroll
    for (int i = 0; i < 4; i++) {
        int d = d0 + ty + i * 8, c = c0 + tx;
        if (d < CLASS_DIM && c < IN_CH)
            g_BT[((size_t)kn * CLASS_DIM + d) * IN_CH + c] = tf32_rne(tile[tx][ty + i * 8]);
    }
}

// ---------------------------------------------------------------------------
// Kernel 1: priors GEMM, single-pass tf32 mma on pre-rounded inputs.
// Per CTA (k<=t, mhalf, nblock): C[128x64] = A[128x600] @ B[600x64].
// 75 K-steps of 8. 4 warps (2m x 2n), warp tile 64x32 (4x4 m16n8k8).
// A smem [c][b] pitch 136 (conflict-free); B smem [n][c] pitch 12.
// Double-buffered, one __syncthreads per step.
// ---------------------------------------------------------------------------
#define PITCHA 136
#define PITCHB 12
#define AWORDS (8 * PITCHA)   // 1088
#define BWORDS (64 * PITCHB)  // 768
#define NSTEP (IN_CH / 8)     // 75

__global__ __launch_bounds__(128) void k_gemm_mma(const int* __restrict__ tptr) {
    int k = blockIdx.z;
    if (k > *tptr) return;
    int b0 = blockIdx.x * 128;
    int g0 = blockIdx.y * 64;

    __shared__ uint32_t S[2 * AWORDS + 2 * BWORDS];  // ~14.8 KB

    int tid = threadIdx.x;
    int lane = tid & 31;
    int wid = tid >> 5;
    int mw = wid & 1, nw = wid >> 1;
    int g = lane >> 2, tg = lane & 3;

    // A staging: 8 c-rows x 128 b, from g_xT (coalesced)
    int arow = tid >> 5;          // 0..3 (+4)
    int acol = (tid & 31) * 4;    // 0..124
    const float* ax = g_xT + ((size_t)k * IN_CH + arow) * BATCH + b0 + acol;

    // B staging: 64 n-rows x 8 c, from g_BT
    int brow = tid >> 1, bcoff = (tid & 1) * 4;
    int gn = g0 + brow;
    bool bval = gn < NFUSED;
    int nr = bval ? (gn / CLASS_DIM) : 0;
    int dr = bval ? (gn - nr * CLASS_DIM) : 0;
    const float* bx = g_BT + ((size_t)(k * CAPS + nr) * CLASS_DIM + dr) * IN_CH + bcoff;

    float acc[4][4][4];
#pragma unroll
    for (int i = 0; i < 4; i++)
#pragma unroll
        for (int j = 0; j < 4; j++)
#pragma unroll
            for (int q = 0; q < 4; q++) acc[i][j][q] = 0.f;

    // Prologue: k-step 0
    uint4 va0 = *reinterpret_cast<const uint4*>(ax);
    uint4 va1 = *reinterpret_cast<const uint4*>(ax + 4 * BATCH);
    uint4 vb = make_uint4(0, 0, 0, 0);
    if (bval) vb = *reinterpret_cast<const uint4*>(bx);

    {
        int ai = arow * PITCHA + acol, bi = brow * PITCHB + bcoff;
        *reinterpret_cast<uint4*>(&S[ai]) = va0;
        *reinterpret_cast<uint4*>(&S[(arow + 4) * PITCHA + acol]) = va1;
        *reinterpret_cast<uint4*>(&S[2 * AWORDS + bi]) = vb;
    }

    for (int ct = 0; ct < NSTEP; ct++) {
        __syncthreads();
        bool more = (ct + 1 < NSTEP);
        if (more) {
            int c = (ct + 1) * 8;
            va0 = *reinterpret_cast<const uint4*>(ax + (size_t)c * BATCH);
            va1 = *reinterpret_cast<const uint4*>(ax + (size_t)(c + 4) * BATCH);
            if (bval) vb = *reinterpret_cast<const uint4*>(bx + c);
        }

        int abuf = (ct & 1) * AWORDS;
        int bbuf = 2 * AWORDS + (ct & 1) * BWORDS;

        // A fragments: a0=A[m=g][c=tg], a1=A[g+8][tg], a2=A[g][tg+4], a3=A[g+8][tg+4]
        uint32_t ah0[4], ah1[4], ah2[4], ah3[4];
#pragma unroll
        for (int i = 0; i < 4; i++) {
            int m = mw * 64 + i * 16 + g;
            ah0[i] = S[abuf + tg * PITCHA + m];
            ah1[i] = S[abuf + tg * PITCHA + m + 8];
            ah2[i] = S[abuf + (tg + 4) * PITCHA + m];
            ah3[i] = S[abuf + (tg + 4) * PITCHA + m + 8];
        }
        // B fragments: b0=B[k=tg][n=r], b1=B[tg+4][r]
        uint32_t bh0[4], bh1[4];
#pragma unroll
        for (int j = 0; j < 4; j++) {
            int r = nw * 32 + j * 8 + g;
            bh0[j] = S[bbuf + r * PITCHB + tg];
            bh1[j] = S[bbuf + r * PITCHB + tg + 4];
        }

#pragma unroll
        for (int i = 0; i < 4; i++)
#pragma unroll
            for (int j = 0; j < 4; j++)
                mma_tf32(acc[i][j], ah0[i], ah1[i], ah2[i], ah3[i], bh0[j], bh1[j]);

        if (more) {
            int na = ((ct + 1) & 1) * AWORDS;
            int nb = 2 * AWORDS + ((ct + 1) & 1) * BWORDS;
            *reinterpret_cast<uint4*>(&S[na + arow * PITCHA + acol]) = va0;
            *reinterpret_cast<uint4*>(&S[na + (arow + 4) * PITCHA + acol]) = va1;
            *reinterpret_cast<uint4*>(&S[nb + brow * PITCHB + bcoff]) = vb;
        }
    }

    // Epilogue: c0,c1 -> row g cols 2tg,2tg+1; c2,c3 -> row g+8
#pragma unroll
    for (int j = 0; j < 4; j++) {
        int gc = g0 + nw * 32 + j * 8 + tg * 2;
        if (gc < NFUSED) {
            int n = gc / CLASS_DIM, d = gc - n * CLASS_DIM;  // gc even -> pair in-region
            float* p = g_P + ((size_t)(n * ADAPTERS + k) * BATCH) * CLASS_DIM + d;
#pragma unroll
            for (int i = 0; i < 4; i++) {
                int mr = b0 + mw * 64 + i * 16 + g;
                *reinterpret_cast<float2*>(p + (size_t)mr * CLASS_DIM) =
                    make_float2(acc[i][j][0], acc[i][j][1]);
                *reinterpret_cast<float2*>(p + (size_t)(mr + 8) * CLASS_DIM) =
                    make_float2(acc[i][j][2], acc[i][j][3]);
            }
        }
    }
}

// ---------------------------------------------------------------------------
// Kernel 2: routing (R10 version). Only k<=t; parallel warp softmax.
// ---------------------------------------------------------------------------
__global__ __launch_bounds__(256) void k_route(const int* __restrict__ tptr,
                                               const float* __restrict__ tsv) {
    __shared__ float Ps[ADAPTERS][CLASS_DIM];
    __shared__ float tsvv[ADAPTERS], maskv[ADAPTERS];
    __shared__ float l[ADAPTERS], probs[ADAPTERS];
    __shared__ float vote[CLASS_DIM], outv[CLASS_DIM];
    __shared__ float coef_s;

    int b = blockIdx.x, n = blockIdx.y;
    int tid = threadIdx.x;
    int t = *tptr;
    int kc = t + 1;

    const float* Pb = g_P + ((size_t)(n * ADAPTERS) * BATCH + b) * CLASS_DIM;
    int nf4 = kc * (CLASS_DIM / 4);
    for (int q = tid; q < nf4; q += 256) {
        int k = q / (CLASS_DIM / 4);
        int r = q - k * (CLASS_DIM / 4);
        float4 v = *reinterpret_cast<const float4*>(Pb + (size_t)k * BATCH * CLASS_DIM + r * 4);
        *reinterpret_cast<float4*>(&Ps[k][r * 4]) = v;
    }
    if (tid < ADAPTERS) {
        float tv = tsv[t * ADAPTERS + tid];
        tsvv[tid] = tv;
        maskv[tid] = (tv == 0.f) ? -10000.f : 0.f;
        l[tid] = 0.f;
    }
    __syncthreads();

    int wrp = tid >> 5, lane = tid & 31;

    for (int it = 0; it < 3; it++) {
        if (tid < 32) {
            float v0 = (tid < kc) ? fmaf(l[tid], tsvv[tid], maskv[tid]) : -3.0e38f;
            float v1 = (tid + 32 < kc) ? fmaf(l[tid + 32], tsvv[tid + 32], maskv[tid + 32]) : -3.0e38f;
            float mx = fmaxf(v0, v1);
#pragma unroll
            for (int o = 16; o > 0; o >>= 1) mx = fmaxf(mx, __shfl_xor_sync(0xffffffff, mx, o));
            float e0 = (tid < kc) ? expf(v0 - mx) : 0.f;
            float e1 = (tid + 32 < kc) ? expf(v1 - mx) : 0.f;
            float sm = e0 + e1;
#pragma unroll
            for (int o = 16; o > 0; o >>= 1) sm += __shfl_xor_sync(0xffffffff, sm, o);
            float inv = 1.f / sm;
            if (tid < kc) probs[tid] = e0 * inv;
            if (tid + 32 < kc) probs[tid + 32] = e1 * inv;
        }
        __syncthreads();

        if (tid < CLASS_DIM) {
            float v = 0.f;
            for (int kk = 0; kk < kc; kk++) v = fmaf(probs[kk], Ps[kk][tid], v);
            vote[tid] = v;
        }
        __syncthreads();
        if (it == 2) break;

        if (tid < 32) {
            float p = 0.f;
            for (int d = tid; d < CLASS_DIM; d += 32) {
                float v = vote[d];
                p = fmaf(v, v, p);
            }
#pragma unroll
            for (int o = 16; o > 0; o >>= 1) p += __shfl_xor_sync(0xffffffff, p, o);
            if (tid == 0) coef_s = sqrtf(p) / (1.f + p);
        }
        __syncthreads();
        if (tid < CLASS_DIM) outv[tid] = vote[tid] * coef_s;
        __syncthreads();

        for (int kk = wrp; kk < kc; kk += 8) {
            float p = 0.f;
            for (int d = lane; d < CLASS_DIM; d += 32) p = fmaf(Ps[kk][d], outv[d], p);
#pragma unroll
            for (int o = 16; o > 0; o >>= 1) p += __shfl_xor_sync(0xffffffff, p, o);
            if (lane == 0) l[kk] += p;
        }
        __syncthreads();
    }

    if (tid < CLASS_DIM) g_V[((size_t)n * BATCH + b) * CLASS_DIM + tid] = vote[tid];
}

// ---------------------------------------------------------------------------
// Kernel 3: expansion. Register-resident gated coefficients; streaming stores.
// ---------------------------------------------------------------------------
#define EXP_SPLIT 8
#define EXP_ROWS (CLASS_DIM / EXP_SPLIT)  // 25

__global__ __launch_bounds__(192) void k_expand(const int* __restrict__ tptr,
                                                const float* __restrict__ s_ptr,
                                                const float* __restrict__ W,
                                                const float* __restrict__ bvec,
                                                const float* __restrict__ el,
                                                float* __restrict__ out) {
    __shared__ float h[CLASS_DIM * CAPS];

    int b2 = blockIdx.x;
    int d2_0 = blockIdx.y * EXP_ROWS;
    int tid = threadIdx.x;
    int t = *tptr;
    float s = s_ptr[0];

    for (int idx = tid; idx < CLASS_DIM * CAPS; idx += 192)
        h[idx] = g_V[(size_t)b2 * (CLASS_DIM * CAPS) + idx];

    int j = tid * 4;
    float4 e4 = *reinterpret_cast<const float4*>(el + (size_t)t * DHID + j);
    float4 b4 = *reinterpret_cast<const float4*>(bvec + j);
    float g0 = 1.f / (1.f + expf(-s * e4.x));
    float g1 = 1.f / (1.f + expf(-s * e4.y));
    float g2 = 1.f / (1.f + expf(-s * e4.z));
    float g3 = 1.f / (1.f + expf(-s * e4.w));
    float4 w0 = *reinterpret_cast<const float4*>(W + j * 3);
    float4 w1 = *reinterpret_cast<const float4*>(W + j * 3 + 4);
    float4 w2 = *reinterpret_cast<const float4*>(W + j * 3 + 8);
    float4 c0 = make_float4(w0.x * g0, w0.y * g0, w0.z * g0, b4.x * g0);
    float4 c1 = make_float4(w0.w * g1, w1.x * g1, w1.y * g1, b4.y * g1);
    float4 c2 = make_float4(w1.z * g2, w1.w * g2, w2.x * g2, b4.z * g2);
    float4 c3 = make_float4(w2.y * g3, w2.z * g3, w2.w * g3, b4.w * g3);
    __syncthreads();

    float* ob = out + (size_t)b2 * CLASS_DIM * DHID + (size_t)d2_0 * DHID + j;
    const float* hp = h + d2_0 * 3;
#pragma unroll 5
    for (int r = 0; r < EXP_ROWS; r++) {
        float h0 = hp[0], h1 = hp[1], h2 = hp[2];
        hp += 3;
        float4 o;
        o.x = fmaf(h0, c0.x, fmaf(h1, c0.y, fmaf(h2, c0.z, c0.w)));
        o.y = fmaf(h0, c1.x, fmaf(h1, c1.y, fmaf(h2, c1.z, c1.w)));
        o.z = fmaf(h0, c2.x, fmaf(h1, c2.y, fmaf(h2, c2.z, c2.w)));
        o.w = fmaf(h0, c3.x, fmaf(h1, c3.y, fmaf(h2, c3.z, c3.w)));
        __stcs(reinterpret_cast<float4*>(ob), o);
        ob += DHID;
    }
}

// ---------------------------------------------------------------------------
extern "C" void kernel_launch(void* const* d_in, const int* in_sizes, int n_in,
                              void* d_out, int out_size) {
    const int* t = (const int*)d_in[0];
    const float* x = (const float*)d_in[1];
    const float* s = (const float*)d_in[2];
    const float* rw = (const float*)d_in[3];
    const float* W = (const float*)d_in[4];
    const float* bb = (const float*)d_in[5];
    const float* el = (const float*)d_in[6];
    const float* tsv = (const float*)d_in[7];
    float* out = (float*)d_out;

    k_transpose<<<dim3(ADAPTERS, (IN_CH + 31) / 32, BATCH / 32), dim3(32, 8)>>>(x, t);
    k_btrans<<<dim3(ADAPTERS * CAPS, (IN_CH + 31) / 32, (CLASS_DIM + 31) / 32), dim3(32, 8)>>>(rw, t);
    k_gemm_mma<<<dim3(2, (NFUSED + 63) / 64, ADAPTERS), 128>>>(t);
    k_route<<<dim3(BATCH, CAPS), 256>>>(t, tsv);
    k_expand<<<dim3(BATCH, EXP_SPLIT), 192>>>(t, s, W, bb, el, out);
}